// round 6
// baseline (speedup 1.0000x reference)
#include <cuda_runtime.h>

// dRMSD, L=2048, B=8 — single fused kernel.
// R6 = R5 hot loop + single-wave residency: __launch_bounds__(128,8) so all
// 1088 blocks (7.35/SM) are resident in one wave (capacity 8), unroll 2 to
// keep regs <= 62 without loop spills.
//
// dx^2 = (|xi|^2 + |xj|^2) + (-2xj).xi
// S_b  = closed_form(sum dx^2+dy^2) - 2 * sum_{i!=j} sqrt(dx^2 * dy^2)

#define BATCH  8
#define NPTS   2047
#define NPAD   2048
#define TS     128
#define NT     (NPAD / TS)                 // 16
#define TPAIRS (NT * (NT + 1) / 2)         // 136
#define NBLK   (BATCH * TPAIRS)            // 1088
#define TPB    128

__device__ float    g_part[NBLK];
__device__ float    g_aux[BATCH][NT][9];   // S|x|^2, Sx(3), S|y|^2, Sy(3), S|x||y|
__device__ unsigned g_count;               // zero-init; reset by last block

typedef unsigned long long u64;

__device__ __forceinline__ u64 pack2(float lo, float hi) {
    u64 r; asm("mov.b64 %0, {%1, %2};" : "=l"(r) : "f"(lo), "f"(hi)); return r;
}
__device__ __forceinline__ void unpack2(u64 v, float& lo, float& hi) {
    asm("mov.b64 {%0, %1}, %2;" : "=f"(lo), "=f"(hi) : "l"(v));
}
__device__ __forceinline__ u64 add2(u64 a, u64 b) {
    u64 r; asm("add.rn.f32x2 %0, %1, %2;" : "=l"(r) : "l"(a), "l"(b)); return r;
}
__device__ __forceinline__ u64 mul2(u64 a, u64 b) {
    u64 r; asm("mul.rn.f32x2 %0, %1, %2;" : "=l"(r) : "l"(a), "l"(b)); return r;
}
__device__ __forceinline__ u64 fma2(u64 a, u64 b, u64 c) {
    u64 r; asm("fma.rn.f32x2 %0, %1, %2, %3;" : "=l"(r) : "l"(a), "l"(b), "l"(c)); return r;
}
__device__ __forceinline__ float sqrt_abs(float x) {
    float r; asm("sqrt.approx.f32 %0, %1;" : "=f"(r) : "f"(fabsf(x))); return r;
}
__device__ __forceinline__ u64 d2u(double d) { return __double_as_longlong(d); }

__global__ __launch_bounds__(TPB, 8) void drmsd_kernel(
    const float* __restrict__ x, const float* __restrict__ y,
    float* __restrict__ out)
{
    int bid = blockIdx.x;
    int b = bid / TPAIRS;
    int t = bid - b * TPAIRS;
    int ti = 0;
    {
        int rl = NT;
        while (t >= rl) { t -= rl; rl--; ti++; }
    }
    int tj = ti + t;
    bool diag = (ti == tj);

    // si: raw i coords + norms;  sj: -2*coords + norms (hot-loop operands)
    __shared__ __align__(16) float si[8][TS];
    __shared__ __align__(16) float sj[8][TS];
    int tid = threadIdx.x;

    // ---- load i-point (one per thread) ----
    float ix0 = 0.f, ix1 = 0.f, ix2 = 0.f, iy0 = 0.f, iy1 = 0.f, iy2 = 0.f;
    {
        int s = ti * TS + tid;
        if (s < NPTS) {
            int base = ((s + 1) * BATCH + b) * 3;
            ix0 = x[base]; ix1 = x[base + 1]; ix2 = x[base + 2];
            iy0 = y[base]; iy1 = y[base + 1]; iy2 = y[base + 2];
        }
    }
    float ipx = ix0 * ix0 + ix1 * ix1 + ix2 * ix2;
    float ipy = iy0 * iy0 + iy1 * iy1 + iy2 * iy2;
    si[0][tid] = ix0; si[1][tid] = ix1; si[2][tid] = ix2; si[3][tid] = ipx;
    si[4][tid] = iy0; si[5][tid] = iy1; si[6][tid] = iy2; si[7][tid] = ipy;

    // ---- load j-point (one per thread), store -2-scaled ----
    {
        int s = tj * TS + tid;
        float jx0 = 0.f, jx1 = 0.f, jx2 = 0.f, jy0 = 0.f, jy1 = 0.f, jy2 = 0.f;
        if (s < NPTS) {
            int base = ((s + 1) * BATCH + b) * 3;
            jx0 = x[base]; jx1 = x[base + 1]; jx2 = x[base + 2];
            jy0 = y[base]; jy1 = y[base + 1]; jy2 = y[base + 2];
        }
        sj[0][tid] = -2.f * jx0; sj[1][tid] = -2.f * jx1; sj[2][tid] = -2.f * jx2;
        sj[3][tid] = jx0 * jx0 + jx1 * jx1 + jx2 * jx2;
        sj[4][tid] = -2.f * jy0; sj[5][tid] = -2.f * jy1; sj[6][tid] = -2.f * jy2;
        sj[7][tid] = jy0 * jy0 + jy1 * jy1 + jy2 * jy2;
    }
    __syncthreads();

    // ---- per-tile moments (diagonal blocks only; block-uniform branch) ----
    if (diag) {
        float v[9] = { ipx, ix0, ix1, ix2, ipy, iy0, iy1, iy2, sqrtf(ipx * ipy) };
        #pragma unroll
        for (int off = 16; off > 0; off >>= 1)
            #pragma unroll
            for (int q = 0; q < 9; q++)
                v[q] += __shfl_down_sync(0xffffffffu, v[q], off);
        __shared__ float waux[TPB / 32][9];
        if ((tid & 31) == 0)
            #pragma unroll
            for (int q = 0; q < 9; q++) waux[tid >> 5][q] = v[q];
        __syncthreads();
        if (tid == 0)
            #pragma unroll
            for (int q = 0; q < 9; q++)
                g_aux[b][ti][q] = waux[0][q] + waux[1][q] + waux[2][q] + waux[3][q];
    }

    // ---- hot loop: 2 i per lane, warp-split j halves ----
    int w = tid >> 5, lane = tid & 31;
    int jbase = (w & 1) * 64;              // warp's j half
    int i0 = (w >> 1) * 64 + lane;         // first i
    int i1 = i0 + 32;                      // second i

    u64 X00 = pack2(si[0][i0], si[0][i0]);
    u64 X01 = pack2(si[1][i0], si[1][i0]);
    u64 X02 = pack2(si[2][i0], si[2][i0]);
    u64 P0x = pack2(si[3][i0], si[3][i0]);
    u64 Y00 = pack2(si[4][i0], si[4][i0]);
    u64 Y01 = pack2(si[5][i0], si[5][i0]);
    u64 Y02 = pack2(si[6][i0], si[6][i0]);
    u64 P0y = pack2(si[7][i0], si[7][i0]);
    u64 X10 = pack2(si[0][i1], si[0][i1]);
    u64 X11 = pack2(si[1][i1], si[1][i1]);
    u64 X12 = pack2(si[2][i1], si[2][i1]);
    u64 P1x = pack2(si[3][i1], si[3][i1]);
    u64 Y10 = pack2(si[4][i1], si[4][i1]);
    u64 Y11 = pack2(si[5][i1], si[5][i1]);
    u64 Y12 = pack2(si[6][i1], si[6][i1]);
    u64 P1y = pack2(si[7][i1], si[7][i1]);

    float s00 = 0.f, s01 = 0.f, s10 = 0.f, s11 = 0.f;

    #pragma unroll 2
    for (int jc = 0; jc < 16; jc++) {
        int jl = jbase + jc * 4;           // warp-uniform -> LDS broadcast
        // ---- x phase ----
        double2 c0 = *reinterpret_cast<const double2*>(&sj[0][jl]);
        double2 c1 = *reinterpret_cast<const double2*>(&sj[1][jl]);
        double2 c2 = *reinterpret_cast<const double2*>(&sj[2][jl]);
        double2 cn = *reinterpret_cast<const double2*>(&sj[3][jl]);
        u64 a0 = d2u(c0.x), b0v = d2u(c0.y);
        u64 a1 = d2u(c1.x), b1v = d2u(c1.y);
        u64 a2 = d2u(c2.x), b2v = d2u(c2.y);
        u64 an = d2u(cn.x), bn  = d2u(cn.y);
        u64 tx0A = fma2(a0, X00, fma2(a1, X01, fma2(a2, X02, add2(an, P0x))));
        u64 tx0B = fma2(b0v, X00, fma2(b1v, X01, fma2(b2v, X02, add2(bn, P0x))));
        u64 tx1A = fma2(a0, X10, fma2(a1, X11, fma2(a2, X12, add2(an, P1x))));
        u64 tx1B = fma2(b0v, X10, fma2(b1v, X11, fma2(b2v, X12, add2(bn, P1x))));
        // ---- y phase ----
        double2 d0 = *reinterpret_cast<const double2*>(&sj[4][jl]);
        double2 d1 = *reinterpret_cast<const double2*>(&sj[5][jl]);
        double2 d2 = *reinterpret_cast<const double2*>(&sj[6][jl]);
        double2 dn = *reinterpret_cast<const double2*>(&sj[7][jl]);
        u64 e0 = d2u(d0.x), f0 = d2u(d0.y);
        u64 e1 = d2u(d1.x), f1 = d2u(d1.y);
        u64 e2 = d2u(d2.x), f2 = d2u(d2.y);
        u64 en = d2u(dn.x), fn = d2u(dn.y);
        u64 ty0A = fma2(e0, Y00, fma2(e1, Y01, fma2(e2, Y02, add2(en, P0y))));
        u64 ty0B = fma2(f0, Y00, fma2(f1, Y01, fma2(f2, Y02, add2(fn, P0y))));
        u64 ty1A = fma2(e0, Y10, fma2(e1, Y11, fma2(e2, Y12, add2(en, P1y))));
        u64 ty1B = fma2(f0, Y10, fma2(f1, Y11, fma2(f2, Y12, add2(fn, P1y))));

        u64 p0A = mul2(tx0A, ty0A);
        u64 p0B = mul2(tx0B, ty0B);
        u64 p1A = mul2(tx1A, ty1A);
        u64 p1B = mul2(tx1B, ty1B);
        float q0, q1, q2, q3, q4, q5, q6, q7;
        unpack2(p0A, q0, q1); unpack2(p0B, q2, q3);
        unpack2(p1A, q4, q5); unpack2(p1B, q6, q7);
        s00 += sqrt_abs(q0); s01 += sqrt_abs(q1);
        s00 += sqrt_abs(q2); s01 += sqrt_abs(q3);
        s10 += sqrt_abs(q4); s11 += sqrt_abs(q5);
        s10 += sqrt_abs(q6); s11 += sqrt_abs(q7);
    }

    float val = (s00 + s01) + (s10 + s11);

    // deterministic block reduce
    #pragma unroll
    for (int off = 16; off > 0; off >>= 1)
        val += __shfl_down_sync(0xffffffffu, val, off);
    __shared__ float wsum[TPB / 32];
    if ((tid & 31) == 0) wsum[tid >> 5] = val;
    __syncthreads();
    if (tid == 0) {
        float s = wsum[0] + wsum[1] + wsum[2] + wsum[3];
        g_part[bid] = diag ? s : 2.0f * s;
    }

    // ---- last-block final reduction ----
    __shared__ bool isLast;
    if (tid == 0) {
        __threadfence();
        unsigned v = atomicAdd(&g_count, 1u);
        isLast = (v == (unsigned)(gridDim.x - 1));
    }
    __syncthreads();
    if (!isLast) return;
    __threadfence();

    int b2 = tid >> 4;                  // 0..7
    int l  = tid & 15;                  // 0..15

    float wacc = 0.f;
    for (int k = l; k < TPAIRS; k += 16)
        wacc += g_part[b2 * TPAIRS + k];
    float a[9];
    #pragma unroll
    for (int q = 0; q < 9; q++) a[q] = g_aux[b2][l][q];

    #pragma unroll
    for (int off = 8; off > 0; off >>= 1) {
        wacc += __shfl_down_sync(0xffffffffu, wacc, off, 16);
        #pragma unroll
        for (int q = 0; q < 9; q++)
            a[q] += __shfl_down_sync(0xffffffffu, a[q], off, 16);
    }

    __shared__ float norms[BATCH];
    if (l == 0) {
        float n = (float)NPTS;
        float T = 2.0f * (n * a[0] - (a[1] * a[1] + a[2] * a[2] + a[3] * a[3]))
                + 2.0f * (n * a[4] - (a[5] * a[5] + a[6] * a[6] + a[7] * a[7]));
        float W = wacc - 2.0f * a[8];   // remove pad-point pairs
        float S = T - 2.0f * W;
        if (S < 0.f) S = 0.f;
        norms[b2] = sqrtf(S);
    }
    __syncthreads();
    if (tid == 0) {
        float tot = 0.f;
        #pragma unroll
        for (int i = 0; i < BATCH; i++) tot += norms[i];
        float n = (float)NPTS;
        out[0] = tot / sqrtf(n * n - n) / (float)BATCH;
        g_count = 0;                    // reset for graph replay
    }
}

extern "C" void kernel_launch(void* const* d_in, const int* in_sizes, int n_in,
                              void* d_out, int out_size) {
    const float* x = (const float*)d_in[0];
    const float* y = (const float*)d_in[1];
    (void)in_sizes; (void)n_in; (void)out_size;
    drmsd_kernel<<<NBLK, TPB>>>(x, y, (float*)d_out);
}

// round 7
// speedup vs baseline: 1.0122x; 1.0122x over previous
#include <cuda_runtime.h>

// dRMSD, L=2048, B=8 — single fused kernel.
// R7 = R5 + fully-unrolled hot loop (immediate LDS offsets, pipelining freedom)
//    + closed-form triangular tile decode (no serial while before LDGs).
//
// dx^2 = (|xi|^2 + |xj|^2) + (-2xj).xi
// S_b  = closed_form(sum dx^2+dy^2) - 2 * sum_{i!=j} sqrt(dx^2 * dy^2)

#define BATCH  8
#define NPTS   2047
#define NPAD   2048
#define TS     128
#define NT     (NPAD / TS)                 // 16
#define TPAIRS (NT * (NT + 1) / 2)         // 136
#define NBLK   (BATCH * TPAIRS)            // 1088
#define TPB    128

__device__ float    g_part[NBLK];
__device__ float    g_aux[BATCH][NT][9];   // S|x|^2, Sx(3), S|y|^2, Sy(3), S|x||y|
__device__ unsigned g_count;               // zero-init; reset by last block

typedef unsigned long long u64;

__device__ __forceinline__ u64 pack2(float lo, float hi) {
    u64 r; asm("mov.b64 %0, {%1, %2};" : "=l"(r) : "f"(lo), "f"(hi)); return r;
}
__device__ __forceinline__ void unpack2(u64 v, float& lo, float& hi) {
    asm("mov.b64 {%0, %1}, %2;" : "=f"(lo), "=f"(hi) : "l"(v));
}
__device__ __forceinline__ u64 add2(u64 a, u64 b) {
    u64 r; asm("add.rn.f32x2 %0, %1, %2;" : "=l"(r) : "l"(a), "l"(b)); return r;
}
__device__ __forceinline__ u64 mul2(u64 a, u64 b) {
    u64 r; asm("mul.rn.f32x2 %0, %1, %2;" : "=l"(r) : "l"(a), "l"(b)); return r;
}
__device__ __forceinline__ u64 fma2(u64 a, u64 b, u64 c) {
    u64 r; asm("fma.rn.f32x2 %0, %1, %2, %3;" : "=l"(r) : "l"(a), "l"(b), "l"(c)); return r;
}
__device__ __forceinline__ float sqrt_abs(float x) {
    float r; asm("sqrt.approx.f32 %0, %1;" : "=f"(r) : "f"(fabsf(x))); return r;
}
__device__ __forceinline__ u64 d2u(double d) { return __double_as_longlong(d); }

__global__ __launch_bounds__(TPB, 7) void drmsd_kernel(
    const float* __restrict__ x, const float* __restrict__ y,
    float* __restrict__ out)
{
    int bid = blockIdx.x;
    int b = bid / TPAIRS;
    int t = bid - b * TPAIRS;
    // closed-form triangular decode: S(k) = k*(33-k)/2, 1089-8*S(k) = (33-2k)^2
    int ti = (int)((33.0f - sqrtf((float)(1089 - 8 * t))) * 0.5f);
    if (ti * (33 - ti) / 2 > t) ti--;                    // fixup (rounding safety)
    if ((ti + 1) * (33 - (ti + 1)) / 2 <= t) ti++;
    int tj = ti + (t - ti * (33 - ti) / 2);
    bool diag = (ti == tj);

    // si: raw i coords + norms;  sj: -2*coords + norms (hot-loop operands)
    __shared__ __align__(16) float si[8][TS];
    __shared__ __align__(16) float sj[8][TS];
    int tid = threadIdx.x;

    // ---- load i-point (one per thread) ----
    float ix0 = 0.f, ix1 = 0.f, ix2 = 0.f, iy0 = 0.f, iy1 = 0.f, iy2 = 0.f;
    {
        int s = ti * TS + tid;
        if (s < NPTS) {
            int base = ((s + 1) * BATCH + b) * 3;
            ix0 = x[base]; ix1 = x[base + 1]; ix2 = x[base + 2];
            iy0 = y[base]; iy1 = y[base + 1]; iy2 = y[base + 2];
        }
    }
    float ipx = ix0 * ix0 + ix1 * ix1 + ix2 * ix2;
    float ipy = iy0 * iy0 + iy1 * iy1 + iy2 * iy2;
    si[0][tid] = ix0; si[1][tid] = ix1; si[2][tid] = ix2; si[3][tid] = ipx;
    si[4][tid] = iy0; si[5][tid] = iy1; si[6][tid] = iy2; si[7][tid] = ipy;

    // ---- load j-point (one per thread), store -2-scaled ----
    {
        int s = tj * TS + tid;
        float jx0 = 0.f, jx1 = 0.f, jx2 = 0.f, jy0 = 0.f, jy1 = 0.f, jy2 = 0.f;
        if (s < NPTS) {
            int base = ((s + 1) * BATCH + b) * 3;
            jx0 = x[base]; jx1 = x[base + 1]; jx2 = x[base + 2];
            jy0 = y[base]; jy1 = y[base + 1]; jy2 = y[base + 2];
        }
        sj[0][tid] = -2.f * jx0; sj[1][tid] = -2.f * jx1; sj[2][tid] = -2.f * jx2;
        sj[3][tid] = jx0 * jx0 + jx1 * jx1 + jx2 * jx2;
        sj[4][tid] = -2.f * jy0; sj[5][tid] = -2.f * jy1; sj[6][tid] = -2.f * jy2;
        sj[7][tid] = jy0 * jy0 + jy1 * jy1 + jy2 * jy2;
    }
    __syncthreads();

    // ---- per-tile moments (diagonal blocks only; block-uniform branch) ----
    if (diag) {
        float v[9] = { ipx, ix0, ix1, ix2, ipy, iy0, iy1, iy2, sqrtf(ipx * ipy) };
        #pragma unroll
        for (int off = 16; off > 0; off >>= 1)
            #pragma unroll
            for (int q = 0; q < 9; q++)
                v[q] += __shfl_down_sync(0xffffffffu, v[q], off);
        __shared__ float waux[TPB / 32][9];
        if ((tid & 31) == 0)
            #pragma unroll
            for (int q = 0; q < 9; q++) waux[tid >> 5][q] = v[q];
        __syncthreads();
        if (tid == 0)
            #pragma unroll
            for (int q = 0; q < 9; q++)
                g_aux[b][ti][q] = waux[0][q] + waux[1][q] + waux[2][q] + waux[3][q];
    }

    // ---- hot loop: 2 i per lane, warp-split j halves, FULL unroll ----
    int w = tid >> 5, lane = tid & 31;
    int jbase = (w & 1) * 64;              // warp's j half
    int i0 = (w >> 1) * 64 + lane;         // first i
    int i1 = i0 + 32;                      // second i

    u64 X00 = pack2(si[0][i0], si[0][i0]);
    u64 X01 = pack2(si[1][i0], si[1][i0]);
    u64 X02 = pack2(si[2][i0], si[2][i0]);
    u64 P0x = pack2(si[3][i0], si[3][i0]);
    u64 Y00 = pack2(si[4][i0], si[4][i0]);
    u64 Y01 = pack2(si[5][i0], si[5][i0]);
    u64 Y02 = pack2(si[6][i0], si[6][i0]);
    u64 P0y = pack2(si[7][i0], si[7][i0]);
    u64 X10 = pack2(si[0][i1], si[0][i1]);
    u64 X11 = pack2(si[1][i1], si[1][i1]);
    u64 X12 = pack2(si[2][i1], si[2][i1]);
    u64 P1x = pack2(si[3][i1], si[3][i1]);
    u64 Y10 = pack2(si[4][i1], si[4][i1]);
    u64 Y11 = pack2(si[5][i1], si[5][i1]);
    u64 Y12 = pack2(si[6][i1], si[6][i1]);
    u64 P1y = pack2(si[7][i1], si[7][i1]);

    // base pointer for this warp's j half; all loop offsets compile-time
    const float* sjb = &sj[0][jbase];

    float s00 = 0.f, s01 = 0.f, s10 = 0.f, s11 = 0.f;

    #pragma unroll
    for (int jc = 0; jc < 16; jc++) {
        const int o = jc * 4;              // immediate
        // ---- x phase ----
        double2 c0 = *reinterpret_cast<const double2*>(sjb + 0 * TS + o);
        double2 c1 = *reinterpret_cast<const double2*>(sjb + 1 * TS + o);
        double2 c2 = *reinterpret_cast<const double2*>(sjb + 2 * TS + o);
        double2 cn = *reinterpret_cast<const double2*>(sjb + 3 * TS + o);
        u64 a0 = d2u(c0.x), b0v = d2u(c0.y);
        u64 a1 = d2u(c1.x), b1v = d2u(c1.y);
        u64 a2 = d2u(c2.x), b2v = d2u(c2.y);
        u64 an = d2u(cn.x), bn  = d2u(cn.y);
        u64 tx0A = fma2(a0, X00, fma2(a1, X01, fma2(a2, X02, add2(an, P0x))));
        u64 tx0B = fma2(b0v, X00, fma2(b1v, X01, fma2(b2v, X02, add2(bn, P0x))));
        u64 tx1A = fma2(a0, X10, fma2(a1, X11, fma2(a2, X12, add2(an, P1x))));
        u64 tx1B = fma2(b0v, X10, fma2(b1v, X11, fma2(b2v, X12, add2(bn, P1x))));
        // ---- y phase ----
        double2 d0 = *reinterpret_cast<const double2*>(sjb + 4 * TS + o);
        double2 d1 = *reinterpret_cast<const double2*>(sjb + 5 * TS + o);
        double2 d2 = *reinterpret_cast<const double2*>(sjb + 6 * TS + o);
        double2 dn = *reinterpret_cast<const double2*>(sjb + 7 * TS + o);
        u64 e0 = d2u(d0.x), f0 = d2u(d0.y);
        u64 e1 = d2u(d1.x), f1 = d2u(d1.y);
        u64 e2 = d2u(d2.x), f2 = d2u(d2.y);
        u64 en = d2u(dn.x), fn = d2u(dn.y);
        u64 ty0A = fma2(e0, Y00, fma2(e1, Y01, fma2(e2, Y02, add2(en, P0y))));
        u64 ty0B = fma2(f0, Y00, fma2(f1, Y01, fma2(f2, Y02, add2(fn, P0y))));
        u64 ty1A = fma2(e0, Y10, fma2(e1, Y11, fma2(e2, Y12, add2(en, P1y))));
        u64 ty1B = fma2(f0, Y10, fma2(f1, Y11, fma2(f2, Y12, add2(fn, P1y))));

        u64 p0A = mul2(tx0A, ty0A);
        u64 p0B = mul2(tx0B, ty0B);
        u64 p1A = mul2(tx1A, ty1A);
        u64 p1B = mul2(tx1B, ty1B);
        float q0, q1, q2, q3, q4, q5, q6, q7;
        unpack2(p0A, q0, q1); unpack2(p0B, q2, q3);
        unpack2(p1A, q4, q5); unpack2(p1B, q6, q7);
        s00 += sqrt_abs(q0); s01 += sqrt_abs(q1);
        s00 += sqrt_abs(q2); s01 += sqrt_abs(q3);
        s10 += sqrt_abs(q4); s11 += sqrt_abs(q5);
        s10 += sqrt_abs(q6); s11 += sqrt_abs(q7);
    }

    float val = (s00 + s01) + (s10 + s11);

    // deterministic block reduce
    #pragma unroll
    for (int off = 16; off > 0; off >>= 1)
        val += __shfl_down_sync(0xffffffffu, val, off);
    __shared__ float wsum[TPB / 32];
    if ((tid & 31) == 0) wsum[tid >> 5] = val;
    __syncthreads();
    if (tid == 0) {
        float s = wsum[0] + wsum[1] + wsum[2] + wsum[3];
        g_part[bid] = diag ? s : 2.0f * s;
    }

    // ---- last-block final reduction ----
    __shared__ bool isLast;
    if (tid == 0) {
        __threadfence();
        unsigned v = atomicAdd(&g_count, 1u);
        isLast = (v == (unsigned)(gridDim.x - 1));
    }
    __syncthreads();
    if (!isLast) return;
    __threadfence();

    int b2 = tid >> 4;                  // 0..7
    int l  = tid & 15;                  // 0..15

    float wacc = 0.f;
    for (int k = l; k < TPAIRS; k += 16)
        wacc += g_part[b2 * TPAIRS + k];
    float a[9];
    #pragma unroll
    for (int q = 0; q < 9; q++) a[q] = g_aux[b2][l][q];

    #pragma unroll
    for (int off = 8; off > 0; off >>= 1) {
        wacc += __shfl_down_sync(0xffffffffu, wacc, off, 16);
        #pragma unroll
        for (int q = 0; q < 9; q++)
            a[q] += __shfl_down_sync(0xffffffffu, a[q], off, 16);
    }

    __shared__ float norms[BATCH];
    if (l == 0) {
        float n = (float)NPTS;
        float T = 2.0f * (n * a[0] - (a[1] * a[1] + a[2] * a[2] + a[3] * a[3]))
                + 2.0f * (n * a[4] - (a[5] * a[5] + a[6] * a[6] + a[7] * a[7]));
        float W = wacc - 2.0f * a[8];   // remove pad-point pairs
        float S = T - 2.0f * W;
        if (S < 0.f) S = 0.f;
        norms[b2] = sqrtf(S);
    }
    __syncthreads();
    if (tid == 0) {
        float tot = 0.f;
        #pragma unroll
        for (int i = 0; i < BATCH; i++) tot += norms[i];
        float n = (float)NPTS;
        out[0] = tot / sqrtf(n * n - n) / (float)BATCH;
        g_count = 0;                    // reset for graph replay
    }
}

extern "C" void kernel_launch(void* const* d_in, const int* in_sizes, int n_in,
                              void* d_out, int out_size) {
    const float* x = (const float*)d_in[0];
    const float* y = (const float*)d_in[1];
    (void)in_sizes; (void)n_in; (void)out_size;
    drmsd_kernel<<<NBLK, TPB>>>(x, y, (float*)d_out);
}